// round 16
// baseline (speedup 1.0000x reference)
#include <cuda_runtime.h>
#include <cuda_fp16.h>
#include <cstdint>

#define BATCH 2
#define SEQ   4096
#define DM    512
#define NH    8
#define DKH   64
#define MROWS (BATCH*SEQ)   // 8192

// Scratch (allocation-free rule: __device__ globals). All single fp16.
__device__ uint16_t g_xqh[(size_t)MROWS*DM];
__device__ uint16_t g_xkh[(size_t)MROWS*DM];
__device__ uint16_t g_xvh[(size_t)MROWS*DM];
__device__ uint16_t g_wqh[DM*DM];
__device__ uint16_t g_wkh[DM*DM];
__device__ uint16_t g_wvh[DM*DM];
__device__ uint16_t g_woh[DM*DM];
__device__ uint16_t g_ath[(size_t)MROWS*DM];
__device__ uint16_t g_qhi[BATCH*NH*SEQ*DKH];
__device__ uint16_t g_khi[BATCH*NH*SEQ*DKH], g_vhi[BATCH*NH*SEQ*DKH];

#define QSCALE 0.18033688011112042f   // 0.125 * log2(e): exp(s) = exp2(s')

// ===========================================================================
// PTX helpers (sm_80+ — safe on ptxas target sm_103)
// ===========================================================================
__device__ __forceinline__ uint32_t smem_u32(const void* p) {
    uint32_t a;
    asm("{ .reg .u64 t; cvta.to.shared.u64 t, %1; cvt.u32.u64 %0, t; }" : "=r"(a) : "l"(p));
    return a;
}
__device__ __forceinline__ void ldsm_x4(uint32_t* r, uint32_t addr) {
    asm volatile("ldmatrix.sync.aligned.m8n8.x4.shared.b16 {%0,%1,%2,%3}, [%4];"
                 : "=r"(r[0]), "=r"(r[1]), "=r"(r[2]), "=r"(r[3]) : "r"(addr));
}
__device__ __forceinline__ void ldsm_x4_t(uint32_t* r, uint32_t addr) {
    asm volatile("ldmatrix.sync.aligned.m8n8.x4.trans.shared.b16 {%0,%1,%2,%3}, [%4];"
                 : "=r"(r[0]), "=r"(r[1]), "=r"(r[2]), "=r"(r[3]) : "r"(addr));
}
__device__ __forceinline__ void mma_f16(float* c, const uint32_t* a, uint32_t b0, uint32_t b1) {
    asm volatile("mma.sync.aligned.m16n8k16.row.col.f32.f16.f16.f32 "
                 "{%0,%1,%2,%3}, {%4,%5,%6,%7}, {%8,%9}, {%0,%1,%2,%3};"
                 : "+f"(c[0]), "+f"(c[1]), "+f"(c[2]), "+f"(c[3])
                 : "r"(a[0]), "r"(a[1]), "r"(a[2]), "r"(a[3]), "r"(b0), "r"(b1));
}
#define CP_ASYNC16(dst, src) \
    asm volatile("cp.async.cg.shared.global [%0], [%1], 16;" :: "r"(dst), "l"(src))
#define CP_COMMIT() asm volatile("cp.async.commit_group;" ::: "memory")
#define CP_WAIT0()  asm volatile("cp.async.wait_group 0;" ::: "memory")

#define ONES_H2 0x3C003C00u   // fp16x2 {1.0, 1.0}

__device__ __forceinline__ uint32_t pack_f16x2(float lo, float hi) {
    uint32_t r;
    asm("cvt.rn.f16x2.f32 %0, %1, %2;" : "=r"(r) : "f"(hi), "f"(lo));
    return r;
}
__device__ __forceinline__ uint32_t ex2_h2(uint32_t s) {
    uint32_t r;
    asm("ex2.approx.f16x2 %0, %1;" : "=r"(r) : "r"(s));
    return r;
}

// ===========================================================================
// Convert: fp32 -> single fp16
// ===========================================================================
__global__ __launch_bounds__(256)
void cvt_f16_kernel(const float* __restrict__ src, uint16_t* __restrict__ hi, int n)
{
    const int i = (blockIdx.x*blockDim.x + threadIdx.x) * 4;
    if (i >= n) return;
    float4 v = *(const float4*)(src + i);
    *(uint32_t*)(hi + i)     = pack_f16x2(v.x, v.y);
    *(uint32_t*)(hi + i + 2) = pack_f16x2(v.z, v.w);
}

// ===========================================================================
// Projection GEMM: fp16 1-term, cp.async double buffer, PKC=64.
// CTA 128x64, 8 warps. Row stride 144B (64 data fp16 + 8 pad).
// mode 0: f32 out [rows, D]. mode 1: single fp16, head layout (K/V).
// mode 2: single fp16 scaled by QSCALE, head layout (Q).
// ===========================================================================
#define PKC  64
#define PROW 144
#define SXH  0
#define SWH  18432          // 128*144
#define PSTG 27648          // + 64*144
#define PROJ_SMEM (2*PSTG)  // 55296

__global__ __launch_bounds__(256, 2)
void proj_mma_kernel(const uint16_t* __restrict__ Xhi,
                     const uint16_t* __restrict__ Whi,
                     const float* __restrict__ bias, float* __restrict__ outf,
                     uint16_t* __restrict__ ohi, int mode)
{
    extern __shared__ __align__(16) char smp[];
    const uint32_t sbase = smem_u32(smp);
    const int tid  = threadIdx.x;
    const int wid  = tid >> 5;
    const int lane = tid & 31;
    const int m0   = blockIdx.y * 128;
    const int n0   = blockIdx.x * 64;

    const int xr = tid >> 1, xc = (tid & 1) * 32;   // X: 128 rows, 64B/thread
    const int wr = tid >> 2, wc = (tid & 3) * 16;   // W:  64 rows, 32B/thread

    auto prefetch = [&](int kc, int st) {
        const int k0 = kc * PKC;
        const uint32_t b = sbase + st*PSTG;
        const uint32_t sx = (uint32_t)(xr*PROW + xc*2);
        const uint16_t* xsrc = Xhi + (size_t)(m0 + xr)*DM + k0 + xc;
        CP_ASYNC16(b + SXH + sx,      xsrc);
        CP_ASYNC16(b + SXH + sx + 16, xsrc + 8);
        CP_ASYNC16(b + SXH + sx + 32, xsrc + 16);
        CP_ASYNC16(b + SXH + sx + 48, xsrc + 24);
        const uint32_t sw = (uint32_t)(wr*PROW + wc*2);
        const uint16_t* wsrc = Whi + (size_t)(n0 + wr)*DM + k0 + wc;
        CP_ASYNC16(b + SWH + sw,      wsrc);
        CP_ASYNC16(b + SWH + sw + 16, wsrc + 8);
        CP_COMMIT();
    };

    const int afrow = wid*16 + (lane & 15);
    const int afcol = (lane >= 16) ? 8 : 0;
    const int kfrow = (lane & 7) + ((lane >= 16) ? 8 : 0);
    const int kfcol = (lane & 8) ? 8 : 0;

    prefetch(0, 0);
    CP_WAIT0();
    __syncthreads();

    float c[8][4] = {};

    for (int kc = 0; kc < DM/PKC; kc++) {
        const int st = kc & 1;
        if (kc + 1 < DM/PKC) prefetch(kc + 1, st ^ 1);
        const uint32_t bs = sbase + st*PSTG;

        #pragma unroll
        for (int ks = 0; ks < 4; ks++) {
            uint32_t ahi[4];
            const uint32_t offa = (uint32_t)(afrow*PROW + (ks*16 + afcol)*2);
            ldsm_x4(ahi, bs + SXH + offa);
            #pragma unroll
            for (int pp = 0; pp < 2; pp++) {
                const int p0 = pp*2, p1 = pp*2 + 1;
                const uint32_t off0 = (uint32_t)((p0*16 + kfrow)*PROW + (ks*16 + kfcol)*2);
                const uint32_t off1 = (uint32_t)((p1*16 + kfrow)*PROW + (ks*16 + kfcol)*2);
                uint32_t bh0[4], bh1[4];
                ldsm_x4(bh0, bs + SWH + off0);
                ldsm_x4(bh1, bs + SWH + off1);
                mma_f16(c[2*p0],   ahi, bh0[0], bh0[1]);
                mma_f16(c[2*p0+1], ahi, bh0[2], bh0[3]);
                mma_f16(c[2*p1],   ahi, bh1[0], bh1[1]);
                mma_f16(c[2*p1+1], ahi, bh1[2], bh1[3]);
            }
        }
        CP_WAIT0();
        __syncthreads();
    }

    // epilogue
    const int g = lane >> 2, t = lane & 3;
    const int row0 = m0 + wid*16 + g;
    const float sc = (mode == 2) ? QSCALE : 1.0f;
    #pragma unroll
    for (int nt = 0; nt < 8; nt++) {
        const int col = n0 + nt*8 + 2*t;
        const float b0 = bias[col], b1 = bias[col+1];
        float v00 = (c[nt][0] + b0)*sc, v01 = (c[nt][1] + b1)*sc;
        float v10 = (c[nt][2] + b0)*sc, v11 = (c[nt][3] + b1)*sc;
        if (mode == 0) {
            *(float2*)(outf + (size_t)row0*DM + col)     = make_float2(v00, v01);
            *(float2*)(outf + (size_t)(row0+8)*DM + col) = make_float2(v10, v11);
        } else {
            const int h = n0 >> 6, dk = col & 63;
            const int bb0 = row0 >> 12, s0 = row0 & (SEQ-1);
            const int r1 = row0 + 8;
            const int bb1 = r1 >> 12, s1 = r1 & (SEQ-1);
            const size_t i0 = (((size_t)bb0*NH + h)*SEQ + s0)*DKH + dk;
            const size_t i1 = (((size_t)bb1*NH + h)*SEQ + s1)*DKH + dk;
            *(uint32_t*)&ohi[i0] = pack_f16x2(v00, v01);
            *(uint32_t*)&ohi[i1] = pack_f16x2(v10, v11);
        }
    }
}

// ===========================================================================
// Flash attention: fp16 mma.sync single-term MMA1/MMA2 + ones-column,
// ex2.approx.f16x2 softmax, cp.async double buffer with BC=128 stages
// (two 64-key sub-tiles per stage), split-half interleave.
// ===========================================================================
#define BR 128
#define BCS 128              // keys per smem stage
#define OKH 0
#define OVH 18432            // 128*144
#define STG 36864
#define FLASH_SMEM (2*STG)   // 73728

__global__ __launch_bounds__(256, 2)
void flash_mma_kernel(const uint16_t* __restrict__ gQhi,
                      const uint16_t* __restrict__ gKhi, const uint16_t* __restrict__ gVhi,
                      uint16_t* __restrict__ gAth)
{
    extern __shared__ __align__(16) char smc[];
    const uint32_t sbase = smem_u32(smc);

    const int tid  = threadIdx.x;
    const int wid  = tid >> 5;
    const int lane = tid & 31;
    const int bh   = blockIdx.y;
    const int q0   = blockIdx.x * BR;

    const size_t hb_off = (size_t)bh*SEQ*DKH;
    const uint16_t* Qhi = gQhi + hb_off;
    const uint16_t* Khi = gKhi + hb_off;
    const uint16_t* Vhi = gVhi + hb_off;

    const int lrow = tid >> 1;            // 0..127
    const int lcol = (tid & 1) * 32;      // 0, 32 (halves)

    // ---- stage all 128 Q rows through stage-0 K buffer; frags in regs ----
    uint32_t qh[4][4];
    {
        const size_t go = (size_t)(q0 + lrow)*DKH + lcol;
        const uint32_t so = (uint32_t)(lrow*144 + lcol*2);
        *(uint4*)(smc + OKH + so)      = *(const uint4*)(Qhi + go);
        *(uint4*)(smc + OKH + so + 16) = *(const uint4*)(Qhi + go + 8);
        *(uint4*)(smc + OKH + so + 32) = *(const uint4*)(Qhi + go + 16);
        *(uint4*)(smc + OKH + so + 48) = *(const uint4*)(Qhi + go + 24);
        __syncthreads();
        const int frow = wid*16 + (lane & 15);
        const int fcol = (lane >= 16) ? 8 : 0;
        #pragma unroll
        for (int ks = 0; ks < 4; ks++) {
            const uint32_t off = (uint32_t)(frow*144 + (ks*16 + fcol)*2);
            ldsm_x4(qh[ks], sbase + OKH + off);
        }
        __syncthreads();
    }

    const uint32_t s_cp = (uint32_t)(lrow*144 + lcol*2);
    auto prefetch = [&](int kb, int stage) {
        const size_t go = (size_t)(kb*BCS + lrow)*DKH + lcol;
        const uint32_t base = sbase + stage*STG + s_cp;
        const uint16_t* ks = Khi + go;
        const uint16_t* vs = Vhi + go;
        CP_ASYNC16(base + OKH,      ks);
        CP_ASYNC16(base + OKH + 16, ks + 8);
        CP_ASYNC16(base + OKH + 32, ks + 16);
        CP_ASYNC16(base + OKH + 48, ks + 24);
        CP_ASYNC16(base + OVH,      vs);
        CP_ASYNC16(base + OVH + 16, vs + 8);
        CP_ASYNC16(base + OVH + 32, vs + 16);
        CP_ASYNC16(base + OVH + 48, vs + 24);
        CP_COMMIT();
    };

    prefetch(0, 0);
    CP_WAIT0();
    __syncthreads();

    float o[8][4] = {};
    float ol[4] = {};

    const int kfrow = (lane & 7) + ((lane >= 16) ? 8 : 0);
    const int kfcol = (lane & 8) ? 8 : 0;
    const int vfrow = (lane & 7) + ((lane & 8) ? 8 : 0);
    const int vfcol = (lane >= 16) ? 8 : 0;

    for (int kb = 0; kb < SEQ/BCS; kb++) {
        const int cur = kb & 1;
        if (kb + 1 < SEQ/BCS) prefetch(kb + 1, cur ^ 1);
        const uint32_t sK = sbase + cur*STG + OKH;
        const uint32_t sV = sbase + cur*STG + OVH;

        #pragma unroll
        for (int sub = 0; sub < 2; sub++) {
            const int rbase = sub * 64;
            float c[8][4] = {};
            uint32_t ap[4][4];

            // ---- MMA1 half A (key cols 0-31 of sub-tile) ----
            #pragma unroll
            for (int ks = 0; ks < 4; ks++) {
                const uint32_t off0 = (uint32_t)((rbase + 0*16 + kfrow)*144 + (ks*16 + kfcol)*2);
                const uint32_t off1 = (uint32_t)((rbase + 1*16 + kfrow)*144 + (ks*16 + kfcol)*2);
                uint32_t b0[4], b1[4];
                ldsm_x4(b0, sK + off0);
                ldsm_x4(b1, sK + off1);
                mma_f16(c[0], qh[ks], b0[0], b0[1]);
                mma_f16(c[1], qh[ks], b0[2], b0[3]);
                mma_f16(c[2], qh[ks], b1[0], b1[1]);
                mma_f16(c[3], qh[ks], b1[2], b1[3]);
            }
            // ---- MMA1 half B ----
            #pragma unroll
            for (int ks = 0; ks < 4; ks++) {
                const uint32_t off0 = (uint32_t)((rbase + 2*16 + kfrow)*144 + (ks*16 + kfcol)*2);
                const uint32_t off1 = (uint32_t)((rbase + 3*16 + kfrow)*144 + (ks*16 + kfcol)*2);
                uint32_t b0[4], b1[4];
                ldsm_x4(b0, sK + off0);
                ldsm_x4(b1, sK + off1);
                mma_f16(c[4], qh[ks], b0[0], b0[1]);
                mma_f16(c[5], qh[ks], b0[2], b0[3]);
                mma_f16(c[6], qh[ks], b1[0], b1[1]);
                mma_f16(c[7], qh[ks], b1[2], b1[3]);
            }

            // ---- softmax half A (overlaps MMA1 half B drain) ----
            #pragma unroll
            for (int nt = 0; nt < 4; nt++) {
                ap[nt >> 1][(nt & 1)*2 + 0] = ex2_h2(pack_f16x2(c[nt][0], c[nt][1]));
                ap[nt >> 1][(nt & 1)*2 + 1] = ex2_h2(pack_f16x2(c[nt][2], c[nt][3]));
            }
            // ---- MMA2 K-steps 0,1 ----
            #pragma unroll
            for (int ks2 = 0; ks2 < 2; ks2++) {
                #pragma unroll
                for (int pp = 0; pp < 2; pp++) {
                    const int p0 = pp*2, p1 = pp*2 + 1;
                    const uint32_t off0 = (uint32_t)((rbase + ks2*16 + vfrow)*144 + (p0*16 + vfcol)*2);
                    const uint32_t off1 = (uint32_t)((rbase + ks2*16 + vfrow)*144 + (p1*16 + vfcol)*2);
                    uint32_t v0[4], v1[4];
                    ldsm_x4_t(v0, sV + off0);
                    ldsm_x4_t(v1, sV + off1);
                    mma_f16(o[2*p0],   ap[ks2], v0[0], v0[1]);
                    mma_f16(o[2*p0+1], ap[ks2], v0[2], v0[3]);
                    mma_f16(o[2*p1],   ap[ks2], v1[0], v1[1]);
                    mma_f16(o[2*p1+1], ap[ks2], v1[2], v1[3]);
                }
                mma_f16(ol, ap[ks2], ONES_H2, ONES_H2);
            }

            // ---- softmax half B (overlaps MMA2 first half drain) ----
            #pragma unroll
            for (int nt = 4; nt < 8; nt++) {
                ap[nt >> 1][(nt & 1)*2 + 0] = ex2_h2(pack_f16x2(c[nt][0], c[nt][1]));
                ap[nt >> 1][(nt & 1)*2 + 1] = ex2_h2(pack_f16x2(c[nt][2], c[nt][3]));
            }
            // ---- MMA2 K-steps 2,3 ----
            #pragma unroll
            for (int ks2 = 2; ks2 < 4; ks2++) {
                #pragma unroll
                for (int pp = 0; pp < 2; pp++) {
                    const int p0 = pp*2, p1 = pp*2 + 1;
                    const uint32_t off0 = (uint32_t)((rbase + ks2*16 + vfrow)*144 + (p0*16 + vfcol)*2);
                    const uint32_t off1 = (uint32_t)((rbase + ks2*16 + vfrow)*144 + (p1*16 + vfcol)*2);
                    uint32_t v0[4], v1[4];
                    ldsm_x4_t(v0, sV + off0);
                    ldsm_x4_t(v1, sV + off1);
                    mma_f16(o[2*p0],   ap[ks2], v0[0], v0[1]);
                    mma_f16(o[2*p0+1], ap[ks2], v0[2], v0[3]);
                    mma_f16(o[2*p1],   ap[ks2], v1[0], v1[1]);
                    mma_f16(o[2*p1+1], ap[ks2], v1[2], v1[3]);
                }
                mma_f16(ol, ap[ks2], ONES_H2, ONES_H2);
            }
        }

        CP_WAIT0();
        __syncthreads();
    }

    const float inv0 = 1.0f / ol[0];
    const float inv1 = 1.0f / ol[2];

    // ---- write attended [B, S, D] as single fp16 ----
    const int bb = bh >> 3, h = bh & 7;
    const int g = lane >> 2, t = lane & 3;
    const int row0 = q0 + wid*16 + g;
    const size_t i0 = ((size_t)bb*SEQ + row0)*DM + h*DKH + 2*t;
    const size_t i1 = i0 + 8*(size_t)DM;
    #pragma unroll
    for (int dt = 0; dt < 8; dt++) {
        *(uint32_t*)&gAth[i0 + dt*8] = pack_f16x2(o[dt][0]*inv0, o[dt][1]*inv0);
        *(uint32_t*)&gAth[i1 + dt*8] = pack_f16x2(o[dt][2]*inv1, o[dt][3]*inv1);
    }
}

// ===========================================================================
extern "C" void kernel_launch(void* const* d_in, const int* in_sizes, int n_in,
                              void* d_out, int out_size)
{
    (void)in_sizes; (void)n_in; (void)out_size;
    const float* q  = (const float*)d_in[0];
    const float* k  = (const float*)d_in[1];
    const float* v  = (const float*)d_in[2];
    const float* wq = (const float*)d_in[3];
    const float* bq = (const float*)d_in[4];
    const float* wk = (const float*)d_in[5];
    const float* bk = (const float*)d_in[6];
    const float* wv = (const float*)d_in[7];
    const float* bv = (const float*)d_in[8];
    const float* wo = (const float*)d_in[9];
    const float* bo = (const float*)d_in[10];
    float* out = (float*)d_out;

    uint16_t *xqh, *xkh, *xvh;
    uint16_t *wqh, *wkh, *wvh, *woh;
    uint16_t *ath, *pqh, *pkh, *pvh;
    cudaGetSymbolAddress((void**)&xqh, g_xqh);
    cudaGetSymbolAddress((void**)&xkh, g_xkh);
    cudaGetSymbolAddress((void**)&xvh, g_xvh);
    cudaGetSymbolAddress((void**)&wqh, g_wqh);
    cudaGetSymbolAddress((void**)&wkh, g_wkh);
    cudaGetSymbolAddress((void**)&wvh, g_wvh);
    cudaGetSymbolAddress((void**)&woh, g_woh);
    cudaGetSymbolAddress((void**)&ath, g_ath);
    cudaGetSymbolAddress((void**)&pqh, g_qhi);
    cudaGetSymbolAddress((void**)&pkh, g_khi);
    cudaGetSymbolAddress((void**)&pvh, g_vhi);

    static cudaStream_t s1, s2;
    static cudaEvent_t evF, ev1, ev2;
    static int inited = 0;
    if (!inited) {
        cudaFuncSetAttribute(flash_mma_kernel,
                             cudaFuncAttributeMaxDynamicSharedMemorySize, FLASH_SMEM);
        cudaFuncSetAttribute(proj_mma_kernel,
                             cudaFuncAttributeMaxDynamicSharedMemorySize, PROJ_SMEM);
        cudaStreamCreateWithFlags(&s1, cudaStreamNonBlocking);
        cudaStreamCreateWithFlags(&s2, cudaStreamNonBlocking);
        cudaEventCreateWithFlags(&evF, cudaEventDisableTiming);
        cudaEventCreateWithFlags(&ev1, cudaEventDisableTiming);
        cudaEventCreateWithFlags(&ev2, cudaEventDisableTiming);
        inited = 1;
    }

    const int nX = MROWS*DM, nW = DM*DM;
    const int gX = nX/4/256, gW = nW/4/256;
    dim3 pgrid(DM/64, MROWS/128);    // (8, 64)
    dim3 fgrid(SEQ/BR, BATCH*NH);    // (32, 16)

    // ---- fork: Q on default stream, K on s1, V on s2 ----
    cudaEventRecord(evF, 0);
    cudaStreamWaitEvent(s1, evF, 0);
    cudaStreamWaitEvent(s2, evF, 0);

    // Q chain (default stream) — also convert w_o here
    cvt_f16_kernel<<<gW, 256>>>(wo, woh, nW);
    cvt_f16_kernel<<<gX, 256>>>(q,  xqh, nX);
    cvt_f16_kernel<<<gW, 256>>>(wq, wqh, nW);
    proj_mma_kernel<<<pgrid, 256, PROJ_SMEM>>>(xqh, wqh, bq, nullptr, pqh, 2);

    // K chain (s1)
    cvt_f16_kernel<<<gX, 256, 0, s1>>>(k,  xkh, nX);
    cvt_f16_kernel<<<gW, 256, 0, s1>>>(wk, wkh, nW);
    proj_mma_kernel<<<pgrid, 256, PROJ_SMEM, s1>>>(xkh, wkh, bk, nullptr, pkh, 1);
    cudaEventRecord(ev1, s1);

    // V chain (s2)
    cvt_f16_kernel<<<gX, 256, 0, s2>>>(v,  xvh, nX);
    cvt_f16_kernel<<<gW, 256, 0, s2>>>(wv, wvh, nW);
    proj_mma_kernel<<<pgrid, 256, PROJ_SMEM, s2>>>(xvh, wvh, bv, nullptr, pvh, 1);
    cudaEventRecord(ev2, s2);

    // ---- join, then attention + output projection on default stream ----
    cudaStreamWaitEvent(0, ev1, 0);
    cudaStreamWaitEvent(0, ev2, 0);

    flash_mma_kernel<<<fgrid, 256, FLASH_SMEM>>>(pqh, pkh, pvh, ath);
    proj_mma_kernel<<<pgrid, 256, PROJ_SMEM>>>(ath, woh, bo, out, nullptr, 0);
}

// round 17
// speedup vs baseline: 1.1868x; 1.1868x over previous
#include <cuda_runtime.h>
#include <cuda_fp16.h>
#include <cstdint>

#define BATCH 2
#define SEQ   4096
#define DM    512
#define NH    8
#define DKH   64
#define MROWS (BATCH*SEQ)   // 8192

// Scratch (allocation-free rule: __device__ globals). All single fp16.
__device__ uint16_t g_xqh[(size_t)MROWS*DM];
__device__ uint16_t g_xkh[(size_t)MROWS*DM];
__device__ uint16_t g_xvh[(size_t)MROWS*DM];
__device__ uint16_t g_wqh[DM*DM];
__device__ uint16_t g_wkh[DM*DM];
__device__ uint16_t g_wvh[DM*DM];
__device__ uint16_t g_woh[DM*DM];
__device__ uint16_t g_ath[(size_t)MROWS*DM];
__device__ uint16_t g_qhi[BATCH*NH*SEQ*DKH];
__device__ uint16_t g_khi[BATCH*NH*SEQ*DKH], g_vhi[BATCH*NH*SEQ*DKH];

#define QSCALE 0.18033688011112042f   // 0.125 * log2(e): exp(s) = exp2(s')

// ===========================================================================
// PTX helpers (sm_80+ — safe on ptxas target sm_103)
// ===========================================================================
__device__ __forceinline__ uint32_t smem_u32(const void* p) {
    uint32_t a;
    asm("{ .reg .u64 t; cvta.to.shared.u64 t, %1; cvt.u32.u64 %0, t; }" : "=r"(a) : "l"(p));
    return a;
}
__device__ __forceinline__ void ldsm_x4(uint32_t* r, uint32_t addr) {
    asm volatile("ldmatrix.sync.aligned.m8n8.x4.shared.b16 {%0,%1,%2,%3}, [%4];"
                 : "=r"(r[0]), "=r"(r[1]), "=r"(r[2]), "=r"(r[3]) : "r"(addr));
}
__device__ __forceinline__ void ldsm_x4_t(uint32_t* r, uint32_t addr) {
    asm volatile("ldmatrix.sync.aligned.m8n8.x4.trans.shared.b16 {%0,%1,%2,%3}, [%4];"
                 : "=r"(r[0]), "=r"(r[1]), "=r"(r[2]), "=r"(r[3]) : "r"(addr));
}
__device__ __forceinline__ void mma_f16(float* c, const uint32_t* a, uint32_t b0, uint32_t b1) {
    asm volatile("mma.sync.aligned.m16n8k16.row.col.f32.f16.f16.f32 "
                 "{%0,%1,%2,%3}, {%4,%5,%6,%7}, {%8,%9}, {%0,%1,%2,%3};"
                 : "+f"(c[0]), "+f"(c[1]), "+f"(c[2]), "+f"(c[3])
                 : "r"(a[0]), "r"(a[1]), "r"(a[2]), "r"(a[3]), "r"(b0), "r"(b1));
}
#define CP_ASYNC16(dst, src) \
    asm volatile("cp.async.cg.shared.global [%0], [%1], 16;" :: "r"(dst), "l"(src))
#define CP_COMMIT() asm volatile("cp.async.commit_group;" ::: "memory")
#define CP_WAIT0()  asm volatile("cp.async.wait_group 0;" ::: "memory")

#define ONES_H2 0x3C003C00u   // fp16x2 {1.0, 1.0}

__device__ __forceinline__ uint32_t pack_f16x2(float lo, float hi) {
    uint32_t r;
    asm("cvt.rn.f16x2.f32 %0, %1, %2;" : "=r"(r) : "f"(hi), "f"(lo));
    return r;
}
__device__ __forceinline__ uint32_t ex2_h2(uint32_t s) {
    uint32_t r;
    asm("ex2.approx.f16x2 %0, %1;" : "=r"(r) : "r"(s));
    return r;
}

// ===========================================================================
// Convert: fp32 -> single fp16
// ===========================================================================
__global__ __launch_bounds__(256)
void cvt_f16_kernel(const float* __restrict__ src, uint16_t* __restrict__ hi, int n)
{
    const int i = (blockIdx.x*blockDim.x + threadIdx.x) * 4;
    if (i >= n) return;
    float4 v = *(const float4*)(src + i);
    *(uint32_t*)(hi + i)     = pack_f16x2(v.x, v.y);
    *(uint32_t*)(hi + i + 2) = pack_f16x2(v.z, v.w);
}

// ===========================================================================
// Projection GEMM (R15 config — proven): fp16 1-term, cp.async double buffer,
// PKC=32. CTA 128x64, 8 warps.
// mode 0: f32 out [rows, D]. mode 1: single fp16, head layout (K/V).
// mode 2: single fp16 scaled by QSCALE, head layout (Q).
// ===========================================================================
#define PKC  32
#define PROW 80
#define SXH  0
#define SWH  10240
#define PSTG 15360
#define PROJ_SMEM (2*PSTG)   // 30720

__global__ __launch_bounds__(256, 2)
void proj_mma_kernel(const uint16_t* __restrict__ Xhi,
                     const uint16_t* __restrict__ Whi,
                     const float* __restrict__ bias, float* __restrict__ outf,
                     uint16_t* __restrict__ ohi, int mode)
{
    extern __shared__ __align__(16) char smp[];
    const uint32_t sbase = smem_u32(smp);
    const int tid  = threadIdx.x;
    const int wid  = tid >> 5;
    const int lane = tid & 31;
    const int m0   = blockIdx.y * 128;
    const int n0   = blockIdx.x * 64;

    const int xr = tid >> 2, xc = (tid & 3) * 8;

    auto prefetch = [&](int kc, int st) {
        const int k0 = kc * PKC;
        const uint32_t b = sbase + st*PSTG;
        const uint32_t sx = (uint32_t)(xr*PROW + xc*2);
        CP_ASYNC16(b + SXH + sx,            Xhi + (size_t)(m0 + xr)*DM + k0 + xc);
        CP_ASYNC16(b + SXH + sx + 64*PROW,  Xhi + (size_t)(m0 + xr + 64)*DM + k0 + xc);
        CP_ASYNC16(b + SWH + sx,            Whi + (size_t)(n0 + xr)*DM + k0 + xc);
        CP_COMMIT();
    };

    const int afrow = wid*16 + (lane & 15);
    const int afcol = (lane >= 16) ? 8 : 0;
    const int kfrow = (lane & 7) + ((lane >= 16) ? 8 : 0);
    const int kfcol = (lane & 8) ? 8 : 0;

    prefetch(0, 0);
    CP_WAIT0();
    __syncthreads();

    float c[8][4] = {};

    for (int kc = 0; kc < DM/PKC; kc++) {
        const int st = kc & 1;
        if (kc + 1 < DM/PKC) prefetch(kc + 1, st ^ 1);
        const uint32_t bs = sbase + st*PSTG;

        uint32_t ahi[2][4];
        #pragma unroll
        for (int ks = 0; ks < 2; ks++) {
            const uint32_t off = (uint32_t)(afrow*PROW + (ks*16 + afcol)*2);
            ldsm_x4(ahi[ks], bs + SXH + off);
        }
        #pragma unroll
        for (int ks = 0; ks < 2; ks++) {
            #pragma unroll
            for (int pp = 0; pp < 2; pp++) {
                const int p0 = pp*2, p1 = pp*2 + 1;
                const uint32_t off0 = (uint32_t)((p0*16 + kfrow)*PROW + (ks*16 + kfcol)*2);
                const uint32_t off1 = (uint32_t)((p1*16 + kfrow)*PROW + (ks*16 + kfcol)*2);
                uint32_t bh0[4], bh1[4];
                ldsm_x4(bh0, bs + SWH + off0);
                ldsm_x4(bh1, bs + SWH + off1);
                mma_f16(c[2*p0],   ahi[ks], bh0[0], bh0[1]);
                mma_f16(c[2*p0+1], ahi[ks], bh0[2], bh0[3]);
                mma_f16(c[2*p1],   ahi[ks], bh1[0], bh1[1]);
                mma_f16(c[2*p1+1], ahi[ks], bh1[2], bh1[3]);
            }
        }
        CP_WAIT0();
        __syncthreads();
    }

    // epilogue
    const int g = lane >> 2, t = lane & 3;
    const int row0 = m0 + wid*16 + g;
    const float sc = (mode == 2) ? QSCALE : 1.0f;
    #pragma unroll
    for (int nt = 0; nt < 8; nt++) {
        const int col = n0 + nt*8 + 2*t;
        const float b0 = bias[col], b1 = bias[col+1];
        float v00 = (c[nt][0] + b0)*sc, v01 = (c[nt][1] + b1)*sc;
        float v10 = (c[nt][2] + b0)*sc, v11 = (c[nt][3] + b1)*sc;
        if (mode == 0) {
            *(float2*)(outf + (size_t)row0*DM + col)     = make_float2(v00, v01);
            *(float2*)(outf + (size_t)(row0+8)*DM + col) = make_float2(v10, v11);
        } else {
            const int h = n0 >> 6, dk = col & 63;
            const int bb0 = row0 >> 12, s0 = row0 & (SEQ-1);
            const int r1 = row0 + 8;
            const int bb1 = r1 >> 12, s1 = r1 & (SEQ-1);
            const size_t i0 = (((size_t)bb0*NH + h)*SEQ + s0)*DKH + dk;
            const size_t i1 = (((size_t)bb1*NH + h)*SEQ + s1)*DKH + dk;
            *(uint32_t*)&ohi[i0] = pack_f16x2(v00, v01);
            *(uint32_t*)&ohi[i1] = pack_f16x2(v10, v11);
        }
    }
}

// ===========================================================================
// Flash attention (R15 config — proven): fp16 mma.sync single-term MMA1/MMA2
// + ones-column, ex2.approx.f16x2 softmax, cp.async double buffer (BC=64),
// split-half interleave. Epilogue writes attended as single fp16.
// ===========================================================================
#define BR 128
#define BC 64
#define OKH 0
#define OVH 9216
#define STG 18432
#define FLASH_SMEM (2*STG)

__global__ __launch_bounds__(256, 2)
void flash_mma_kernel(const uint16_t* __restrict__ gQhi,
                      const uint16_t* __restrict__ gKhi, const uint16_t* __restrict__ gVhi,
                      uint16_t* __restrict__ gAth)
{
    extern __shared__ __align__(16) char smc[];
    const uint32_t sbase = smem_u32(smc);

    const int tid  = threadIdx.x;
    const int wid  = tid >> 5;
    const int lane = tid & 31;
    const int bh   = blockIdx.y;
    const int q0   = blockIdx.x * BR;

    const size_t hb_off = (size_t)bh*SEQ*DKH;
    const uint16_t* Qhi = gQhi + hb_off;
    const uint16_t* Khi = gKhi + hb_off;
    const uint16_t* Vhi = gVhi + hb_off;

    const int lrow = tid >> 2;
    const int lcol = (tid & 3) * 16;

    uint32_t qh[4][4];
    #pragma unroll
    for (int hbk = 0; hbk < 2; hbk++) {
        const size_t go = (size_t)(q0 + hbk*64 + lrow)*DKH + lcol;
        const uint32_t so = (uint32_t)(lrow*144 + lcol*2);
        *(uint4*)(smc + OKH + so)      = *(const uint4*)(Qhi + go);
        *(uint4*)(smc + OKH + so + 16) = *(const uint4*)(Qhi + go + 8);
        __syncthreads();
        if ((wid >> 2) == hbk) {
            const int frow = (wid & 3)*16 + (lane & 15);
            const int fcol = (lane >= 16) ? 8 : 0;
            #pragma unroll
            for (int ks = 0; ks < 4; ks++) {
                const uint32_t off = (uint32_t)(frow*144 + (ks*16 + fcol)*2);
                ldsm_x4(qh[ks], sbase + OKH + off);
            }
        }
        __syncthreads();
    }

    const uint32_t s_cp = (uint32_t)(lrow*144 + lcol*2);
    auto prefetch = [&](int kb, int stage) {
        const size_t go = (size_t)(kb*BC + lrow)*DKH + lcol;
        const uint32_t base = sbase + stage*STG + s_cp;
        CP_ASYNC16(base + OKH,      Khi + go);
        CP_ASYNC16(base + OKH + 16, Khi + go + 8);
        CP_ASYNC16(base + OVH,      Vhi + go);
        CP_ASYNC16(base + OVH + 16, Vhi + go + 8);
        CP_COMMIT();
    };

    prefetch(0, 0);
    CP_WAIT0();
    __syncthreads();

    float o[8][4] = {};
    float ol[4] = {};

    const int kfrow = (lane & 7) + ((lane >= 16) ? 8 : 0);
    const int kfcol = (lane & 8) ? 8 : 0;
    const int vfrow = (lane & 7) + ((lane & 8) ? 8 : 0);
    const int vfcol = (lane >= 16) ? 8 : 0;

    for (int kb = 0; kb < SEQ/BC; kb++) {
        const int cur = kb & 1;
        if (kb + 1 < SEQ/BC) prefetch(kb + 1, cur ^ 1);
        const uint32_t sK = sbase + cur*STG + OKH;
        const uint32_t sV = sbase + cur*STG + OVH;

        float c[8][4] = {};
        uint32_t ap[4][4];

        #pragma unroll
        for (int ks = 0; ks < 4; ks++) {
            const uint32_t off0 = (uint32_t)((0*16 + kfrow)*144 + (ks*16 + kfcol)*2);
            const uint32_t off1 = (uint32_t)((1*16 + kfrow)*144 + (ks*16 + kfcol)*2);
            uint32_t b0[4], b1[4];
            ldsm_x4(b0, sK + off0);
            ldsm_x4(b1, sK + off1);
            mma_f16(c[0], qh[ks], b0[0], b0[1]);
            mma_f16(c[1], qh[ks], b0[2], b0[3]);
            mma_f16(c[2], qh[ks], b1[0], b1[1]);
            mma_f16(c[3], qh[ks], b1[2], b1[3]);
        }
        #pragma unroll
        for (int ks = 0; ks < 4; ks++) {
            const uint32_t off0 = (uint32_t)((2*16 + kfrow)*144 + (ks*16 + kfcol)*2);
            const uint32_t off1 = (uint32_t)((3*16 + kfrow)*144 + (ks*16 + kfcol)*2);
            uint32_t b0[4], b1[4];
            ldsm_x4(b0, sK + off0);
            ldsm_x4(b1, sK + off1);
            mma_f16(c[4], qh[ks], b0[0], b0[1]);
            mma_f16(c[5], qh[ks], b0[2], b0[3]);
            mma_f16(c[6], qh[ks], b1[0], b1[1]);
            mma_f16(c[7], qh[ks], b1[2], b1[3]);
        }

        #pragma unroll
        for (int nt = 0; nt < 4; nt++) {
            ap[nt >> 1][(nt & 1)*2 + 0] = ex2_h2(pack_f16x2(c[nt][0], c[nt][1]));
            ap[nt >> 1][(nt & 1)*2 + 1] = ex2_h2(pack_f16x2(c[nt][2], c[nt][3]));
        }
        #pragma unroll
        for (int ks2 = 0; ks2 < 2; ks2++) {
            #pragma unroll
            for (int pp = 0; pp < 2; pp++) {
                const int p0 = pp*2, p1 = pp*2 + 1;
                const uint32_t off0 = (uint32_t)((ks2*16 + vfrow)*144 + (p0*16 + vfcol)*2);
                const uint32_t off1 = (uint32_t)((ks2*16 + vfrow)*144 + (p1*16 + vfcol)*2);
                uint32_t v0[4], v1[4];
                ldsm_x4_t(v0, sV + off0);
                ldsm_x4_t(v1, sV + off1);
                mma_f16(o[2*p0],   ap[ks2], v0[0], v0[1]);
                mma_f16(o[2*p0+1], ap[ks2], v0[2], v0[3]);
                mma_f16(o[2*p1],   ap[ks2], v1[0], v1[1]);
                mma_f16(o[2*p1+1], ap[ks2], v1[2], v1[3]);
            }
            mma_f16(ol, ap[ks2], ONES_H2, ONES_H2);
        }

        #pragma unroll
        for (int nt = 4; nt < 8; nt++) {
            ap[nt >> 1][(nt & 1)*2 + 0] = ex2_h2(pack_f16x2(c[nt][0], c[nt][1]));
            ap[nt >> 1][(nt & 1)*2 + 1] = ex2_h2(pack_f16x2(c[nt][2], c[nt][3]));
        }
        #pragma unroll
        for (int ks2 = 2; ks2 < 4; ks2++) {
            #pragma unroll
            for (int pp = 0; pp < 2; pp++) {
                const int p0 = pp*2, p1 = pp*2 + 1;
                const uint32_t off0 = (uint32_t)((ks2*16 + vfrow)*144 + (p0*16 + vfcol)*2);
                const uint32_t off1 = (uint32_t)((ks2*16 + vfrow)*144 + (p1*16 + vfcol)*2);
                uint32_t v0[4], v1[4];
                ldsm_x4_t(v0, sV + off0);
                ldsm_x4_t(v1, sV + off1);
                mma_f16(o[2*p0],   ap[ks2], v0[0], v0[1]);
                mma_f16(o[2*p0+1], ap[ks2], v0[2], v0[3]);
                mma_f16(o[2*p1],   ap[ks2], v1[0], v1[1]);
                mma_f16(o[2*p1+1], ap[ks2], v1[2], v1[3]);
            }
            mma_f16(ol, ap[ks2], ONES_H2, ONES_H2);
        }

        CP_WAIT0();
        __syncthreads();
    }

    const float inv0 = 1.0f / ol[0];
    const float inv1 = 1.0f / ol[2];

    // ---- write attended [B, S, D] as single fp16 ----
    const int bb = bh >> 3, h = bh & 7;
    const int g = lane >> 2, t = lane & 3;
    const int row0 = q0 + wid*16 + g;
    const size_t i0 = ((size_t)bb*SEQ + row0)*DM + h*DKH + 2*t;
    const size_t i1 = i0 + 8*(size_t)DM;
    #pragma unroll
    for (int dt = 0; dt < 8; dt++) {
        *(uint32_t*)&gAth[i0 + dt*8] = pack_f16x2(o[dt][0]*inv0, o[dt][1]*inv0);
        *(uint32_t*)&gAth[i1 + dt*8] = pack_f16x2(o[dt][2]*inv1, o[dt][3]*inv1);
    }
}

// ===========================================================================
extern "C" void kernel_launch(void* const* d_in, const int* in_sizes, int n_in,
                              void* d_out, int out_size)
{
    (void)in_sizes; (void)n_in; (void)out_size;
    const float* q  = (const float*)d_in[0];
    const float* k  = (const float*)d_in[1];
    const float* v  = (const float*)d_in[2];
    const float* wq = (const float*)d_in[3];
    const float* bq = (const float*)d_in[4];
    const float* wk = (const float*)d_in[5];
    const float* bk = (const float*)d_in[6];
    const float* wv = (const float*)d_in[7];
    const float* bv = (const float*)d_in[8];
    const float* wo = (const float*)d_in[9];
    const float* bo = (const float*)d_in[10];
    float* out = (float*)d_out;

    uint16_t *xqh, *xkh, *xvh;
    uint16_t *wqh, *wkh, *wvh, *woh;
    uint16_t *ath, *pqh, *pkh, *pvh;
    cudaGetSymbolAddress((void**)&xqh, g_xqh);
    cudaGetSymbolAddress((void**)&xkh, g_xkh);
    cudaGetSymbolAddress((void**)&xvh, g_xvh);
    cudaGetSymbolAddress((void**)&wqh, g_wqh);
    cudaGetSymbolAddress((void**)&wkh, g_wkh);
    cudaGetSymbolAddress((void**)&wvh, g_wvh);
    cudaGetSymbolAddress((void**)&woh, g_woh);
    cudaGetSymbolAddress((void**)&ath, g_ath);
    cudaGetSymbolAddress((void**)&pqh, g_qhi);
    cudaGetSymbolAddress((void**)&pkh, g_khi);
    cudaGetSymbolAddress((void**)&pvh, g_vhi);

    static cudaStream_t s1, s2;
    static cudaEvent_t evF, ev1, ev2;
    static int inited = 0;
    if (!inited) {
        cudaFuncSetAttribute(flash_mma_kernel,
                             cudaFuncAttributeMaxDynamicSharedMemorySize, FLASH_SMEM);
        cudaFuncSetAttribute(proj_mma_kernel,
                             cudaFuncAttributeMaxDynamicSharedMemorySize, PROJ_SMEM);
        cudaStreamCreateWithFlags(&s1, cudaStreamNonBlocking);
        cudaStreamCreateWithFlags(&s2, cudaStreamNonBlocking);
        cudaEventCreateWithFlags(&evF, cudaEventDisableTiming);
        cudaEventCreateWithFlags(&ev1, cudaEventDisableTiming);
        cudaEventCreateWithFlags(&ev2, cudaEventDisableTiming);
        inited = 1;
    }

    const int nX = MROWS*DM, nW = DM*DM;
    const int gX = nX/4/256, gW = nW/4/256;
    dim3 pgrid(DM/64, MROWS/128);    // (8, 64)
    dim3 fgrid(SEQ/BR, BATCH*NH);    // (32, 16)

    // ---- fork: Q on default stream, K on s1, V on s2 ----
    cudaEventRecord(evF, 0);
    cudaStreamWaitEvent(s1, evF, 0);
    cudaStreamWaitEvent(s2, evF, 0);

    // Q chain (default stream)
    cvt_f16_kernel<<<gX, 256>>>(q,  xqh, nX);
    cvt_f16_kernel<<<gW, 256>>>(wq, wqh, nW);
    proj_mma_kernel<<<pgrid, 256, PROJ_SMEM>>>(xqh, wqh, bq, nullptr, pqh, 2);

    // K chain (s1) — w_o conversion rides here (off the Q critical path;
    // O-projection already waits on ev1)
    cvt_f16_kernel<<<gW, 256, 0, s1>>>(wo, woh, nW);
    cvt_f16_kernel<<<gX, 256, 0, s1>>>(k,  xkh, nX);
    cvt_f16_kernel<<<gW, 256, 0, s1>>>(wk, wkh, nW);
    proj_mma_kernel<<<pgrid, 256, PROJ_SMEM, s1>>>(xkh, wkh, bk, nullptr, pkh, 1);
    cudaEventRecord(ev1, s1);

    // V chain (s2)
    cvt_f16_kernel<<<gX, 256, 0, s2>>>(v,  xvh, nX);
    cvt_f16_kernel<<<gW, 256, 0, s2>>>(wv, wvh, nW);
    proj_mma_kernel<<<pgrid, 256, PROJ_SMEM, s2>>>(xvh, wvh, bv, nullptr, pvh, 1);
    cudaEventRecord(ev2, s2);

    // ---- join, then attention + output projection on default stream ----
    cudaStreamWaitEvent(0, ev1, 0);
    cudaStreamWaitEvent(0, ev2, 0);

    flash_mma_kernel<<<fgrid, 256, FLASH_SMEM>>>(pqh, pkh, pvh, ath);
    proj_mma_kernel<<<pgrid, 256, PROJ_SMEM>>>(ath, woh, bo, out, nullptr, 0);
}